// round 1
// baseline (speedup 1.0000x reference)
#include <cuda_runtime.h>
#include <math.h>

#define BB 16
#define TT 28
#define NN 2048
#define HH 32
#define LL 8

// -------- scratch (device globals; no allocation allowed) --------
__device__ float g_Qt[BB*HH*NN];   // Q transposed [b][h][n], pre-scaled by (1-geo)/sqrt(H)*log2e
__device__ float g_Kt[BB*HH*NN];   // K transposed [b][h][n]
__device__ float g_V [BB*NN*HH];   // V natural    [b][n][h]
__device__ float g_ds[BB*NN];      // delayed signal [b][n]

// =====================================================================
// Kernel 1: delayed signal  ds[b,n] = sum_tau softmax(logits)[tau] * x[b, T-1-tau, n]
// =====================================================================
__global__ void ds_kernel(const float* __restrict__ x, const float* __restrict__ logits)
{
    int b = blockIdx.y;
    int n = blockIdx.x * 256 + threadIdx.x;
    float lw[LL];
    float m = -1e30f;
#pragma unroll
    for (int t = 0; t < LL; t++) { lw[t] = logits[t]; m = fmaxf(m, lw[t]); }
    float s = 0.f, e[LL];
#pragma unroll
    for (int t = 0; t < LL; t++) { e[t] = expf(lw[t] - m); s += e[t]; }
    float inv = 1.f / s;
    float acc = 0.f;
#pragma unroll
    for (int tau = 0; tau < LL; tau++) {
        acc += e[tau] * inv * x[((size_t)b * TT + (TT - 1 - tau)) * NN + n];
    }
    g_ds[b * NN + n] = acc;
}

// =====================================================================
// Kernel 2: QKV projections.
//   Qt[b][j][n] = cs * (f[b,n,:] . Wq[j,:] + bq[j]),  cs = (1-geo)/sqrt(H)*log2e
//   Kt[b][j][n] =       f . Wk[j,:] + bk[j]
//   V [b][n][j] =       f . Wv[j,:] + bv[j]   (staged via smem for coalesced store)
// =====================================================================
__global__ void qkv_kernel(const float* __restrict__ features,
                           const float* __restrict__ Wq, const float* __restrict__ bq,
                           const float* __restrict__ Wk, const float* __restrict__ bk,
                           const float* __restrict__ Wv, const float* __restrict__ bv,
                           const float* __restrict__ gw)
{
    __shared__ float Ws[3][32 * 32];   // [j][h], stride 32 (broadcast reads, float4-aligned)
    __shared__ float bs[3][32];
    __shared__ float vsm[256 * 33];    // V staging [row][j], stride 33 (conflict-free)

    int b = blockIdx.y;
    int n0 = blockIdx.x * 256;
    int tid = threadIdx.x;

    for (int i = tid; i < 1024; i += 256) {
        Ws[0][i] = Wq[i]; Ws[1][i] = Wk[i]; Ws[2][i] = Wv[i];
    }
    if (tid < 32) { bs[0][tid] = bq[tid]; bs[1][tid] = bk[tid]; bs[2][tid] = bv[tid]; }
    __syncthreads();

    float geo = 1.f / (1.f + expf(-gw[0]));
    float csq = (1.f - geo) * 0.17677669529663687f * 1.4426950408889634f; // (1-geo)/sqrt(32)*log2e

    int n = n0 + tid;
    float4 rf[8];
    const float* fp = features + ((size_t)b * NN + n) * HH;
#pragma unroll
    for (int i = 0; i < 8; i++) rf[i] = *(const float4*)(fp + i * 4);

#pragma unroll 4
    for (int j = 0; j < 32; j++) {
        float aq = bs[0][j], ak = bs[1][j], av = bs[2][j];
#pragma unroll
        for (int i = 0; i < 8; i++) {
            float4 wq4 = *(float4*)&Ws[0][j * 32 + i * 4];
            float4 wk4 = *(float4*)&Ws[1][j * 32 + i * 4];
            float4 wv4 = *(float4*)&Ws[2][j * 32 + i * 4];
            aq += rf[i].x * wq4.x + rf[i].y * wq4.y + rf[i].z * wq4.z + rf[i].w * wq4.w;
            ak += rf[i].x * wk4.x + rf[i].y * wk4.y + rf[i].z * wk4.z + rf[i].w * wk4.w;
            av += rf[i].x * wv4.x + rf[i].y * wv4.y + rf[i].z * wv4.z + rf[i].w * wv4.w;
        }
        g_Qt[((size_t)b * HH + j) * NN + n] = csq * aq;
        g_Kt[((size_t)b * HH + j) * NN + n] = ak;
        vsm[tid * 33 + j] = av;
    }
    __syncthreads();
    // coalesced V store
    for (int ch = 0; ch < 32; ch++) {
        int idx = ch * 256 + tid;
        int r = idx >> 5, h = idx & 31;
        g_V[((size_t)b * NN + n0 + r) * HH + h] = vsm[r * 33 + h];
    }
}

// =====================================================================
// Kernel 3: fused flash-attention + propagation + output proj + LayerNorm.
//   CTA = 64 query rows x 1 batch. Loop over key tiles of 128.
//   s' = Qt.K + (geo*5*log2e)*adj   (already in log2 domain)
//   online softmax; attended & propagated accumulated; epilogue fused.
// =====================================================================
#define SMEM_FLOATS 19584
#define SMEM_BYTES  (SMEM_FLOATS * 4)

__global__ void __launch_bounds__(256, 2) attn_kernel(
    const float* __restrict__ adj, const float* __restrict__ features,
    const float* __restrict__ gw,  const float* __restrict__ Wo,
    const float* __restrict__ bo,  const float* __restrict__ gamma,
    const float* __restrict__ beta, float* __restrict__ out)
{
    extern __shared__ float smbuf[];
    float* Qs   = smbuf;          // [32][64]   2048
    float* Ks   = smbuf + 2048;   // [32][128]  4096  (reused as epilogue scratch)
    float* Vs   = smbuf + 6144;   // [128][36]  4608
    float* Ps   = smbuf + 10752;  // [64][132]  8448
    float* dss  = smbuf + 19200;  // [128]
    float* m_s  = smbuf + 19328;  // [64]
    float* l_s  = smbuf + 19392;  // [64]
    float* pr_s = smbuf + 19456;  // [64]
    float* al_s = smbuf + 19520;  // [64]
    // epilogue aliases (over dead Ps region)
    float* Cs  = smbuf + 10752;           // [64][33]
    float* Wos = smbuf + 10752 + 64 * 33; // [32][33]
    float* bos = Wos + 32 * 33;
    float* gms = bos + 32;
    float* bts = gms + 32;

    const int b   = blockIdx.y;
    const int n0  = blockIdx.x * 64;
    const int tid = threadIdx.x;
    const int ty  = tid >> 4;          // 0..15 : rows ty*4..ty*4+3   (S phase)
    const int tx  = tid & 15;          // cols tx*4 and 64+tx*4       (S phase)
    const int t   = tid & 127;
    const int rg  = (t >> 3) << 2;     // PV: row base (4 rows)
    const int hg  = (t & 7) << 2;      // PV: h base (4 cols)
    const int ch0 = (tid >> 7) << 6;   // PV: c half 0 or 64

    const float LOG2E = 1.4426950408889634f;
    float geo = 1.f / (1.f + expf(-gw[0]));
    float cg  = geo * 5.f * LOG2E;

    // load Q tile (stays resident)
    for (int i = tid; i < 512; i += 256) {
        int k = i >> 4, r = (i & 15) << 2;
        *(float4*)&Qs[k * 64 + r] = *(const float4*)&g_Qt[((size_t)b * HH + k) * NN + n0 + r];
    }
    if (tid < 64) { m_s[tid] = -INFINITY; l_s[tid] = 0.f; pr_s[tid] = 0.f; al_s[tid] = 0.f; }

    float acc[4][4];
#pragma unroll
    for (int i = 0; i < 4; i++)
#pragma unroll
        for (int j = 0; j < 4; j++) acc[i][j] = 0.f;

    for (int m0 = 0; m0 < NN; m0 += 128) {
        __syncthreads();   // prev PV done; Q/stat init visible on first iter
        // load K tile [k][c]
        for (int i = tid; i < 1024; i += 256) {
            int k = i >> 5, c = (i & 31) << 2;
            *(float4*)&Ks[k * 128 + c] = *(const float4*)&g_Kt[((size_t)b * HH + k) * NN + m0 + c];
        }
        // load V tile [c][h]
        for (int i = tid; i < 1024; i += 256) {
            int c = i >> 3, h = (i & 7) << 2;
            *(float4*)&Vs[c * 36 + h] = *(const float4*)&g_V[((size_t)b * NN + m0 + c) * HH + h];
        }
        if (tid < 128) dss[tid] = g_ds[b * NN + m0 + tid];
        __syncthreads();

        // ---- S = Qs^T Ks (+ cg*adj), 4 rows x (4+4) cols per thread ----
        float s0[4][4], s1[4][4];
#pragma unroll
        for (int i = 0; i < 4; i++) {
            const float* arow = adj + (size_t)(n0 + ty * 4 + i) * NN + m0;
            float4 a0 = *(const float4*)&arow[tx * 4];
            float4 a1 = *(const float4*)&arow[64 + tx * 4];
            s0[i][0] = cg * a0.x; s0[i][1] = cg * a0.y; s0[i][2] = cg * a0.z; s0[i][3] = cg * a0.w;
            s1[i][0] = cg * a1.x; s1[i][1] = cg * a1.y; s1[i][2] = cg * a1.z; s1[i][3] = cg * a1.w;
        }
#pragma unroll
        for (int k = 0; k < 32; k++) {
            float4 q  = *(float4*)&Qs[k * 64 + ty * 4];
            float4 ka = *(float4*)&Ks[k * 128 + tx * 4];
            float4 kb = *(float4*)&Ks[k * 128 + 64 + tx * 4];
            float qv[4] = {q.x, q.y, q.z, q.w};
#pragma unroll
            for (int i = 0; i < 4; i++) {
                s0[i][0] += qv[i] * ka.x; s0[i][1] += qv[i] * ka.y;
                s0[i][2] += qv[i] * ka.z; s0[i][3] += qv[i] * ka.w;
                s1[i][0] += qv[i] * kb.x; s1[i][1] += qv[i] * kb.y;
                s1[i][2] += qv[i] * kb.z; s1[i][3] += qv[i] * kb.w;
            }
        }
        // ---- online softmax (16-lane groups own a row) ----
#pragma unroll
        for (int i = 0; i < 4; i++) {
            int r = ty * 4 + i;
            float rm = s0[i][0];
#pragma unroll
            for (int j = 1; j < 4; j++) rm = fmaxf(rm, s0[i][j]);
#pragma unroll
            for (int j = 0; j < 4; j++) rm = fmaxf(rm, s1[i][j]);
#pragma unroll
            for (int off = 1; off < 16; off <<= 1)
                rm = fmaxf(rm, __shfl_xor_sync(0xffffffffu, rm, off, 16));
            float mo = m_s[r];
            float mn = fmaxf(mo, rm);
            float al = exp2f(mo - mn);          // 0 when mo == -inf
            float sum = 0.f, pr = 0.f;
#pragma unroll
            for (int j = 0; j < 4; j++) {
                float p = exp2f(s0[i][j] - mn); s0[i][j] = p; sum += p; pr += p * dss[tx * 4 + j];
            }
#pragma unroll
            for (int j = 0; j < 4; j++) {
                float p = exp2f(s1[i][j] - mn); s1[i][j] = p; sum += p; pr += p * dss[64 + tx * 4 + j];
            }
#pragma unroll
            for (int off = 1; off < 16; off <<= 1) {
                sum += __shfl_xor_sync(0xffffffffu, sum, off, 16);
                pr  += __shfl_xor_sync(0xffffffffu, pr,  off, 16);
            }
            *(float4*)&Ps[r * 132 + tx * 4]      = make_float4(s0[i][0], s0[i][1], s0[i][2], s0[i][3]);
            *(float4*)&Ps[r * 132 + 64 + tx * 4] = make_float4(s1[i][0], s1[i][1], s1[i][2], s1[i][3]);
            if (tx == 0) {
                m_s[r]  = mn;
                al_s[r] = al;
                l_s[r]  = l_s[r]  * al + sum;
                pr_s[r] = pr_s[r] * al + pr;
            }
        }
        __syncthreads();

        // ---- PV: acc += P * V  (c-range split across thread halves) ----
        {
            float a0 = al_s[rg + 0], a1 = al_s[rg + 1], a2 = al_s[rg + 2], a3 = al_s[rg + 3];
#pragma unroll
            for (int j = 0; j < 4; j++) { acc[0][j] *= a0; acc[1][j] *= a1; acc[2][j] *= a2; acc[3][j] *= a3; }
#pragma unroll 2
            for (int c0 = ch0; c0 < ch0 + 64; c0 += 4) {
                float4 p0 = *(float4*)&Ps[(rg + 0) * 132 + c0];
                float4 p1 = *(float4*)&Ps[(rg + 1) * 132 + c0];
                float4 p2 = *(float4*)&Ps[(rg + 2) * 132 + c0];
                float4 p3 = *(float4*)&Ps[(rg + 3) * 132 + c0];
                float4 v0 = *(float4*)&Vs[(c0 + 0) * 36 + hg];
                float4 v1 = *(float4*)&Vs[(c0 + 1) * 36 + hg];
                float4 v2 = *(float4*)&Vs[(c0 + 2) * 36 + hg];
                float4 v3 = *(float4*)&Vs[(c0 + 3) * 36 + hg];
                acc[0][0] += p0.x*v0.x + p0.y*v1.x + p0.z*v2.x + p0.w*v3.x;
                acc[0][1] += p0.x*v0.y + p0.y*v1.y + p0.z*v2.y + p0.w*v3.y;
                acc[0][2] += p0.x*v0.z + p0.y*v1.z + p0.z*v2.z + p0.w*v3.z;
                acc[0][3] += p0.x*v0.w + p0.y*v1.w + p0.z*v2.w + p0.w*v3.w;
                acc[1][0] += p1.x*v0.x + p1.y*v1.x + p1.z*v2.x + p1.w*v3.x;
                acc[1][1] += p1.x*v0.y + p1.y*v1.y + p1.z*v2.y + p1.w*v3.y;
                acc[1][2] += p1.x*v0.z + p1.y*v1.z + p1.z*v2.z + p1.w*v3.z;
                acc[1][3] += p1.x*v0.w + p1.y*v1.w + p1.z*v2.w + p1.w*v3.w;
                acc[2][0] += p2.x*v0.x + p2.y*v1.x + p2.z*v2.x + p2.w*v3.x;
                acc[2][1] += p2.x*v0.y + p2.y*v1.y + p2.z*v2.y + p2.w*v3.y;
                acc[2][2] += p2.x*v0.z + p2.y*v1.z + p2.z*v2.z + p2.w*v3.z;
                acc[2][3] += p2.x*v0.w + p2.y*v1.w + p2.z*v2.w + p2.w*v3.w;
                acc[3][0] += p3.x*v0.x + p3.y*v1.x + p3.z*v2.x + p3.w*v3.x;
                acc[3][1] += p3.x*v0.y + p3.y*v1.y + p3.z*v2.y + p3.w*v3.y;
                acc[3][2] += p3.x*v0.z + p3.y*v1.z + p3.z*v2.z + p3.w*v3.z;
                acc[3][3] += p3.x*v0.w + p3.y*v1.w + p3.z*v2.w + p3.w*v3.w;
            }
        }
    }
    __syncthreads();

    // ---- epilogue: merge acc halves, combined, out-proj, LayerNorm ----
    if (tid >= 128) {
#pragma unroll
        for (int i = 0; i < 4; i++)
            *(float4*)&Ks[(rg + i) * 32 + hg] = make_float4(acc[i][0], acc[i][1], acc[i][2], acc[i][3]);
    }
    for (int i = tid; i < 1024; i += 256) Wos[(i >> 5) * 33 + (i & 31)] = Wo[i];
    if (tid < 32) { bos[tid] = bo[tid]; gms[tid] = gamma[tid]; bts[tid] = beta[tid]; }
    __syncthreads();

    if (tid < 128) {
#pragma unroll
        for (int i = 0; i < 4; i++) {
            int r = rg + i;
            float invl = 1.f / l_s[r];
            float pv   = pr_s[r] * invl * 0.1f;
            float4 fb  = *(const float4*)&features[((size_t)b * NN + n0 + r) * HH + hg];
            float4 hi  = *(float4*)&Ks[r * 32 + hg];
            Cs[r * 33 + hg + 0] = fb.x + (acc[i][0] + hi.x) * invl + pv;
            Cs[r * 33 + hg + 1] = fb.y + (acc[i][1] + hi.y) * invl + pv;
            Cs[r * 33 + hg + 2] = fb.z + (acc[i][2] + hi.z) * invl + pv;
            Cs[r * 33 + hg + 3] = fb.w + (acc[i][3] + hi.w) * invl + pv;
        }
    }
    __syncthreads();

    if (tid < 64) {
        float cr[32], ho[32];
#pragma unroll
        for (int h = 0; h < 32; h++) cr[h] = Cs[tid * 33 + h];
        float mu = 0.f;
#pragma unroll
        for (int j = 0; j < 32; j++) {
            float a = bos[j];
#pragma unroll
            for (int h = 0; h < 32; h++) a += cr[h] * Wos[j * 33 + h];
            ho[j] = a; mu += a;
        }
        mu *= 0.03125f;
        float var = 0.f;
#pragma unroll
        for (int j = 0; j < 32; j++) { float d = ho[j] - mu; var += d * d; }
        var *= 0.03125f;
        float rs = rsqrtf(var + 1e-5f);
        float* op = out + ((size_t)b * NN + n0 + tid) * HH;
#pragma unroll
        for (int j = 0; j < 32; j++) op[j] = (ho[j] - mu) * rs * gms[j] + bts[j];
    }
}

// =====================================================================
extern "C" void kernel_launch(void* const* d_in, const int* in_sizes, int n_in,
                              void* d_out, int out_size)
{
    const float* x        = (const float*)d_in[0];
    const float* features = (const float*)d_in[1];
    const float* dlog     = (const float*)d_in[2];
    const float* Wq       = (const float*)d_in[3];
    const float* bq       = (const float*)d_in[4];
    const float* Wk       = (const float*)d_in[5];
    const float* bk       = (const float*)d_in[6];
    const float* Wv       = (const float*)d_in[7];
    const float* bv       = (const float*)d_in[8];
    const float* adj      = (const float*)d_in[9];
    const float* gw       = (const float*)d_in[10];
    const float* Wo       = (const float*)d_in[11];
    const float* bo       = (const float*)d_in[12];
    const float* gamma    = (const float*)d_in[13];
    const float* beta     = (const float*)d_in[14];
    float* out = (float*)d_out;

    cudaFuncSetAttribute(attn_kernel, cudaFuncAttributeMaxDynamicSharedMemorySize, SMEM_BYTES);

    ds_kernel<<<dim3(NN / 256, BB), 256>>>(x, dlog);
    qkv_kernel<<<dim3(NN / 256, BB), 256>>>(features, Wq, bq, Wk, bk, Wv, bv, gw);
    attn_kernel<<<dim3(NN / 64, BB), 256, SMEM_BYTES>>>(adj, features, gw, Wo, bo, gamma, beta, out);
}